// round 3
// baseline (speedup 1.0000x reference)
#include <cuda_runtime.h>

#define B_  8
#define S_  512
#define E_  128
#define H_  512
#define BS_ (B_ * S_)      // 4096
#define O_  (E_ * E_)      // 16384

// Persistent scratch (static __device__ — no runtime allocation)
__device__ float g_hidden[BS_ * H_];                 // 8 MB   [bs][h]
__device__ float g_Wa[(size_t)BS_ * O_];             // 268 MB [bs][o], o = d*128+e

// ---------------------------------------------------------------------------
// XLA/Eigen fast tanh for f32 (generic_fast_tanh_float), exact coefficient
// and operation order: clamp to +-7.90531110763549805, Horner with FMA,
// p = x*P(x^2), q = Q(x^2), result p/q (IEEE div), |x|<0.0004 -> x.
// ---------------------------------------------------------------------------
__device__ __forceinline__ float tanh_xla(float x) {
    const float kClamp = 7.90531110763549805f;
    float ax = fabsf(x);
    float xc = fmaxf(-kClamp, fminf(kClamp, x));
    float x2 = xc * xc;
    float p = fmaf(x2, -2.76076847742355e-16f, 2.00018790482477e-13f);
    p = fmaf(x2, p, -8.60467152213735e-11f);
    p = fmaf(x2, p,  5.12229709037114e-08f);
    p = fmaf(x2, p,  1.48572235717979e-05f);
    p = fmaf(x2, p,  6.37261928875436e-04f);
    p = fmaf(x2, p,  4.89352455891786e-03f);
    p = xc * p;
    float q = fmaf(x2, 1.19825839466702e-06f, 1.18534705686654e-04f);
    q = fmaf(x2, q, 2.26843463243900e-03f);
    q = fmaf(x2, q, 4.89352518554385e-03f);
    float r = p / q;
    return (ax < 0.0004f) ? x : r;
}

// ---------------------------------------------------------------------------
// Kernel 1: hidden[bs][h] = tanh_xla( (seq-e FMA chain of X[bs,e]*W1[h,e]) + b1[h] )
// 512 blocks x 256 threads; each block does 8 consecutive bs rows.
// ---------------------------------------------------------------------------
__global__ void hidden_kernel(const float* __restrict__ X,
                              const float* __restrict__ W1,
                              const float* __restrict__ b1) {
    const int row0 = blockIdx.x * 8;
    const int t    = threadIdx.x;

    __shared__ float x_s[E_][8];   // [e][r]

    for (int i = t; i < 8 * E_; i += 256) {
        int r = i >> 7;
        int e = i & 127;
        x_s[e][r] = X[(row0 + r) * E_ + e];
    }
    __syncthreads();

    for (int h = t; h < H_; h += 256) {
        float a0 = 0.f, a1 = 0.f, a2 = 0.f, a3 = 0.f;
        float a4 = 0.f, a5 = 0.f, a6 = 0.f, a7 = 0.f;
        const float* w = W1 + (size_t)h * E_;
#pragma unroll 4
        for (int e = 0; e < E_; e++) {       // strictly ascending e, one chain each
            float wv = w[e];
            float4 xa = *(const float4*)&x_s[e][0];
            float4 xb = *(const float4*)&x_s[e][4];
            a0 = fmaf(xa.x, wv, a0); a1 = fmaf(xa.y, wv, a1);
            a2 = fmaf(xa.z, wv, a2); a3 = fmaf(xa.w, wv, a3);
            a4 = fmaf(xb.x, wv, a4); a5 = fmaf(xb.y, wv, a5);
            a6 = fmaf(xb.z, wv, a6); a7 = fmaf(xb.w, wv, a7);
        }
        float bias = b1[h];
        g_hidden[(size_t)(row0 + 0) * H_ + h] = tanh_xla(a0 + bias);
        g_hidden[(size_t)(row0 + 1) * H_ + h] = tanh_xla(a1 + bias);
        g_hidden[(size_t)(row0 + 2) * H_ + h] = tanh_xla(a2 + bias);
        g_hidden[(size_t)(row0 + 3) * H_ + h] = tanh_xla(a3 + bias);
        g_hidden[(size_t)(row0 + 4) * H_ + h] = tanh_xla(a4 + bias);
        g_hidden[(size_t)(row0 + 5) * H_ + h] = tanh_xla(a5 + bias);
        g_hidden[(size_t)(row0 + 6) * H_ + h] = tanh_xla(a6 + bias);
        g_hidden[(size_t)(row0 + 7) * H_ + h] = tanh_xla(a7 + bias);
    }
}

// ---------------------------------------------------------------------------
// Kernel 2: Wa[bs][o] = (seq-h FMA chain of hidden[bs,h]*W2[o,h]) + b2[o]
// Tile: 128 o x 128 bs per block; 256 threads; per-thread 8x8 register tile
// with strided (x16) output indices for conflict-free smem reads.
// Accumulation: k (=h) strictly ascending, single accumulator per output.
// ---------------------------------------------------------------------------
#define BO  128
#define BBS 128
#define KC  32

__global__ void __launch_bounds__(256, 2)
wa_kernel(const float* __restrict__ W2, const float* __restrict__ b2) {
    const int obase  = blockIdx.x * BO;
    const int bsbase = blockIdx.y * BBS;
    const int tid    = threadIdx.x;
    const int to = tid & 15;     // o  = obase  + to + 16*i
    const int tb = tid >> 4;     // bs = bsbase + tb + 16*j

    __shared__ float w_s[BO][KC + 1];   // [o][k], padded
    __shared__ float h_s[BBS][KC + 1];  // [bs][k], padded

    float acc[8][8];
#pragma unroll
    for (int i = 0; i < 8; i++)
#pragma unroll
        for (int j = 0; j < 8; j++) acc[i][j] = 0.f;

    const int r   = tid >> 1;          // row 0..127
    const int seg = (tid & 1) * 16;    // 16 floats per thread

    for (int kc = 0; kc < H_; kc += KC) {
        // stage tiles (float4 global loads, scalar smem stores)
        const float* wsrc = W2 + (size_t)(obase + r) * H_ + kc + seg;
        const float* hsrc = g_hidden + (size_t)(bsbase + r) * H_ + kc + seg;
#pragma unroll
        for (int v = 0; v < 4; v++) {
            float4 wv4 = *(const float4*)(wsrc + v * 4);
            float4 hv4 = *(const float4*)(hsrc + v * 4);
            w_s[r][seg + v * 4 + 0] = wv4.x; w_s[r][seg + v * 4 + 1] = wv4.y;
            w_s[r][seg + v * 4 + 2] = wv4.z; w_s[r][seg + v * 4 + 3] = wv4.w;
            h_s[r][seg + v * 4 + 0] = hv4.x; h_s[r][seg + v * 4 + 1] = hv4.y;
            h_s[r][seg + v * 4 + 2] = hv4.z; h_s[r][seg + v * 4 + 3] = hv4.w;
        }
        __syncthreads();

#pragma unroll
        for (int k = 0; k < KC; k++) {   // k ascending — order-critical
            float wv[8], hv[8];
#pragma unroll
            for (int i = 0; i < 8; i++) wv[i] = w_s[to + 16 * i][k];
#pragma unroll
            for (int j = 0; j < 8; j++) hv[j] = h_s[tb + 16 * j][k];
#pragma unroll
            for (int i = 0; i < 8; i++)
#pragma unroll
                for (int j = 0; j < 8; j++)
                    acc[i][j] = fmaf(hv[j], wv[i], acc[i][j]);
        }
        __syncthreads();
    }

    // epilogue: + b2, write Wa[bs][o]
#pragma unroll
    for (int i = 0; i < 8; i++) {
        int o = obase + to + 16 * i;
        float bias = b2[o];
#pragma unroll
        for (int j = 0; j < 8; j++) {
            int bs = bsbase + tb + 16 * j;
            g_Wa[(size_t)bs * O_ + o] = acc[i][j] + bias;
        }
    }
}

// ---------------------------------------------------------------------------
// Kernel 3: recurrence. Batches independent -> one block per b, NO global sync.
// et[b,e] <- clip( seq-d FMA chain of et[b,d] * Wa[b,s,d,e] ), emit per step.
// ---------------------------------------------------------------------------
__global__ void __launch_bounds__(E_, 1)
recur_kernel(const float* __restrict__ e0, float* __restrict__ out) {
    const int b = blockIdx.x;      // 0..7
    const int e = threadIdx.x;     // 0..127

    __shared__ float et_s[E_];

    float v = e0[e];
    out[((size_t)b * S_ + 0) * E_ + e] = v;
    et_s[e] = v;
    __syncthreads();

    for (int s = 1; s < S_; s++) {
        const float* wa = g_Wa + ((size_t)(b * S_ + s)) * O_ + e;
        float acc = 0.f;
#pragma unroll 16
        for (int d = 0; d < E_; d++)           // d ascending — order-critical
            acc = fmaf(et_s[d], wa[(size_t)d * E_], acc);
        float nv = fminf(5.0f, fmaxf(-5.0f, acc));
        out[((size_t)b * S_ + s) * E_ + e] = nv;
        __syncthreads();
        et_s[e] = nv;
        __syncthreads();
    }
}

extern "C" void kernel_launch(void* const* d_in, const int* in_sizes, int n_in,
                              void* d_out, int out_size) {
    const float* X  = (const float*)d_in[0];   // [8,512,128]
    const float* W1 = (const float*)d_in[1];   // [512,128]
    const float* b1 = (const float*)d_in[2];   // [512]
    const float* W2 = (const float*)d_in[3];   // [16384,512]
    const float* b2 = (const float*)d_in[4];   // [16384]
    const float* e0 = (const float*)d_in[5];   // [1,128]
    float* out = (float*)d_out;                // [8,512,128] float32

    hidden_kernel<<<BS_ / 8, 256>>>(X, W1, b1);
    dim3 gridB(O_ / BO, BS_ / BBS);
    wa_kernel<<<gridB, 256>>>(W2, b2);
    recur_kernel<<<B_, E_>>>(e0, out);
}

// round 4
// speedup vs baseline: 2.2441x; 2.2441x over previous
#include <cuda_runtime.h>
#include <cstdint>

#define B_  8
#define S_  512
#define E_  128
#define H_  512
#define BS_ (B_ * S_)      // 4096
#define O_  (E_ * E_)      // 16384

// Persistent scratch (static __device__ — no runtime allocation)
__device__ float g_hidden[BS_ * H_];                 // 8 MB   [bs][h]
__device__ float g_Wa[(size_t)BS_ * O_];             // 268 MB [bs][o], o = d*128+e

// ---------------------------------------------------------------------------
// XLA/Eigen fast tanh for f32 — exact coefficients and op order (bit-critical)
// ---------------------------------------------------------------------------
__device__ __forceinline__ float tanh_xla(float x) {
    const float kClamp = 7.90531110763549805f;
    float ax = fabsf(x);
    float xc = fmaxf(-kClamp, fminf(kClamp, x));
    float x2 = xc * xc;
    float p = fmaf(x2, -2.76076847742355e-16f, 2.00018790482477e-13f);
    p = fmaf(x2, p, -8.60467152213735e-11f);
    p = fmaf(x2, p,  5.12229709037114e-08f);
    p = fmaf(x2, p,  1.48572235717979e-05f);
    p = fmaf(x2, p,  6.37261928875436e-04f);
    p = fmaf(x2, p,  4.89352455891786e-03f);
    p = xc * p;
    float q = fmaf(x2, 1.19825839466702e-06f, 1.18534705686654e-04f);
    q = fmaf(x2, q, 2.26843463243900e-03f);
    q = fmaf(x2, q, 4.89352518554385e-03f);
    float r = p / q;
    return (ax < 0.0004f) ? x : r;
}

// ---------------------------------------------------------------------------
// packed f32x2 helpers (bitwise: IEEE fma per 32-bit half, pairing is across
// two DIFFERENT outputs — each output's chain stays a single sequential chain)
// ---------------------------------------------------------------------------
__device__ __forceinline__ void ffma2_(unsigned long long& d,
                                       unsigned long long a,
                                       unsigned long long b) {
    asm("fma.rn.f32x2 %0, %1, %2, %0;" : "+l"(d) : "l"(a), "l"(b));
}
__device__ __forceinline__ unsigned long long dupf_(float x) {
    unsigned long long r;
    unsigned u = __float_as_uint(x);
    asm("mov.b64 %0, {%1, %1};" : "=l"(r) : "r"(u));
    return r;
}
__device__ __forceinline__ float lo_(unsigned long long a) {
    return __uint_as_float((unsigned)(a & 0xffffffffull));
}
__device__ __forceinline__ float hi_(unsigned long long a) {
    return __uint_as_float((unsigned)(a >> 32));
}

// ---------------------------------------------------------------------------
// mbarrier / cp.async.bulk helpers for the recurrence pipeline
// ---------------------------------------------------------------------------
__device__ __forceinline__ void mbar_init_(uint32_t a, uint32_t cnt) {
    asm volatile("mbarrier.init.shared.b64 [%0], %1;" :: "r"(a), "r"(cnt) : "memory");
}
__device__ __forceinline__ void mbar_expect_tx_(uint32_t a, uint32_t bytes) {
    asm volatile("mbarrier.arrive.expect_tx.shared.b64 _, [%0], %1;"
                 :: "r"(a), "r"(bytes) : "memory");
}
__device__ __forceinline__ void bulk_g2s_(uint32_t dst, const void* src,
                                          uint32_t bytes, uint32_t mbar) {
    asm volatile("cp.async.bulk.shared::cluster.global.mbarrier::complete_tx::bytes "
                 "[%0], [%1], %2, [%3];"
                 :: "r"(dst), "l"(src), "r"(bytes), "r"(mbar) : "memory");
}
__device__ __forceinline__ void mbar_wait_(uint32_t a, uint32_t parity) {
    asm volatile(
        "{\n\t.reg .pred P;\n\t"
        "WL%=:\n\t"
        "mbarrier.try_wait.parity.acquire.cta.shared::cta.b64 P, [%0], %1, 0x989680;\n\t"
        "@P bra WD%=;\n\t"
        "bra WL%=;\n\t"
        "WD%=:\n\t}"
        :: "r"(a), "r"(parity) : "memory");
}

// ---------------------------------------------------------------------------
// Kernel 1: hidden[bs][h] = tanh_xla( seq-e FMA chain + b1[h] )  (unchanged)
// ---------------------------------------------------------------------------
__global__ void hidden_kernel(const float* __restrict__ X,
                              const float* __restrict__ W1,
                              const float* __restrict__ b1) {
    const int row0 = blockIdx.x * 8;
    const int t    = threadIdx.x;

    __shared__ float x_s[E_][8];

    for (int i = t; i < 8 * E_; i += 256) {
        int r = i >> 7;
        int e = i & 127;
        x_s[e][r] = X[(row0 + r) * E_ + e];
    }
    __syncthreads();

    for (int h = t; h < H_; h += 256) {
        float a0 = 0.f, a1 = 0.f, a2 = 0.f, a3 = 0.f;
        float a4 = 0.f, a5 = 0.f, a6 = 0.f, a7 = 0.f;
        const float* w = W1 + (size_t)h * E_;
#pragma unroll 4
        for (int e = 0; e < E_; e++) {
            float wv = w[e];
            float4 xa = *(const float4*)&x_s[e][0];
            float4 xb = *(const float4*)&x_s[e][4];
            a0 = fmaf(xa.x, wv, a0); a1 = fmaf(xa.y, wv, a1);
            a2 = fmaf(xa.z, wv, a2); a3 = fmaf(xa.w, wv, a3);
            a4 = fmaf(xb.x, wv, a4); a5 = fmaf(xb.y, wv, a5);
            a6 = fmaf(xb.z, wv, a6); a7 = fmaf(xb.w, wv, a7);
        }
        float bias = b1[h];
        g_hidden[(size_t)(row0 + 0) * H_ + h] = tanh_xla(a0 + bias);
        g_hidden[(size_t)(row0 + 1) * H_ + h] = tanh_xla(a1 + bias);
        g_hidden[(size_t)(row0 + 2) * H_ + h] = tanh_xla(a2 + bias);
        g_hidden[(size_t)(row0 + 3) * H_ + h] = tanh_xla(a3 + bias);
        g_hidden[(size_t)(row0 + 4) * H_ + h] = tanh_xla(a4 + bias);
        g_hidden[(size_t)(row0 + 5) * H_ + h] = tanh_xla(a5 + bias);
        g_hidden[(size_t)(row0 + 6) * H_ + h] = tanh_xla(a6 + bias);
        g_hidden[(size_t)(row0 + 7) * H_ + h] = tanh_xla(a7 + bias);
    }
}

// ---------------------------------------------------------------------------
// Kernel 2: Wa[bs][o] = (seq-h FMA chain of hidden[bs,h]*W2[o,h]) + b2[o]
// FFMA2 version: acc pairs over o (adjacent o indices), k strictly ascending.
// smem transposed to [k][row] so o/bs pairs load as 8B LDS.
// ---------------------------------------------------------------------------
#define BO  128
#define BBS 128
#define KC  32

__global__ void __launch_bounds__(256, 2)
wa_kernel(const float* __restrict__ W2, const float* __restrict__ b2) {
    const int obase  = blockIdx.x * BO;
    const int bsbase = blockIdx.y * BBS;
    const int tid    = threadIdx.x;
    const int to = tid & 15;     // o  pairs: 2*to + 32*i, i=0..3
    const int tb = tid >> 4;     // bs pairs: 2*tb + 32*j, j=0..3

    __shared__ __align__(16) float w_s[KC][BO];    // [k][o]
    __shared__ __align__(16) float h_s[KC][BBS];   // [k][bs]

    // accp[i][2j+half] = packed pair (o0, o0+1) accumulator for bs = 2tb+32j+half
    unsigned long long accp[4][8];
#pragma unroll
    for (int i = 0; i < 4; i++)
#pragma unroll
        for (int j = 0; j < 8; j++) accp[i][j] = 0ull;

    const int r   = tid >> 1;          // row 0..127
    const int seg = (tid & 1) * 16;    // 16 k-values per thread

    for (int kc = 0; kc < H_; kc += KC) {
        const float* wsrc = W2 + (size_t)(obase + r) * H_ + kc + seg;
        const float* hsrc = g_hidden + (size_t)(bsbase + r) * H_ + kc + seg;
#pragma unroll
        for (int v = 0; v < 4; v++) {
            float4 w4 = *(const float4*)(wsrc + v * 4);
            float4 h4 = *(const float4*)(hsrc + v * 4);
            w_s[seg + v * 4 + 0][r] = w4.x; w_s[seg + v * 4 + 1][r] = w4.y;
            w_s[seg + v * 4 + 2][r] = w4.z; w_s[seg + v * 4 + 3][r] = w4.w;
            h_s[seg + v * 4 + 0][r] = h4.x; h_s[seg + v * 4 + 1][r] = h4.y;
            h_s[seg + v * 4 + 2][r] = h4.z; h_s[seg + v * 4 + 3][r] = h4.w;
        }
        __syncthreads();

#pragma unroll
        for (int k = 0; k < KC; k++) {   // k strictly ascending — order-critical
            unsigned long long wv2[4];
#pragma unroll
            for (int i = 0; i < 4; i++)
                wv2[i] = *(const unsigned long long*)&w_s[k][2 * to + 32 * i];
#pragma unroll
            for (int j = 0; j < 4; j++) {
                float2 hv = *(const float2*)&h_s[k][2 * tb + 32 * j];
                unsigned long long dl = dupf_(hv.x);
                unsigned long long dh = dupf_(hv.y);
#pragma unroll
                for (int i = 0; i < 4; i++) {
                    ffma2_(accp[i][2 * j + 0], wv2[i], dl);
                    ffma2_(accp[i][2 * j + 1], wv2[i], dh);
                }
            }
        }
        __syncthreads();
    }

    // epilogue: + b2, float2 stores (o0 even -> 8B aligned)
#pragma unroll
    for (int i = 0; i < 4; i++) {
        int o0 = obase + 2 * to + 32 * i;
        float blo = b2[o0];
        float bhi = b2[o0 + 1];
#pragma unroll
        for (int j = 0; j < 4; j++) {
#pragma unroll
            for (int half = 0; half < 2; half++) {
                int bs = bsbase + 2 * tb + 32 * j + half;
                unsigned long long a = accp[i][2 * j + half];
                float2 res = make_float2(lo_(a) + blo, hi_(a) + bhi);
                *(float2*)&g_Wa[(size_t)bs * O_ + o0] = res;
            }
        }
    }
}

// ---------------------------------------------------------------------------
// Kernel 3: recurrence with triple-buffered TMA bulk prefetch.
// One block per batch b; 128 threads (thread = e). Arithmetic identical to the
// passing round-2 version (seq-d FMA chain from smem, clip). Wa tile for step
// s+3 is prefetched while step s computes.
// ---------------------------------------------------------------------------
#define STAGES 3
#define TILE_BYTES_R (O_ * 4)   // 65536

__global__ void __launch_bounds__(E_, 1)
recur_kernel(const float* __restrict__ e0, float* __restrict__ out) {
    extern __shared__ float wa_buf[];            // STAGES * O_ floats (192 KB)
    __shared__ float et_s[E_];
    __shared__ __align__(8) unsigned long long mbar[STAGES];

    const int b = blockIdx.x;      // 0..7
    const int e = threadIdx.x;     // 0..127

    uint32_t mb[STAGES];
#pragma unroll
    for (int i = 0; i < STAGES; i++)
        mb[i] = (uint32_t)__cvta_generic_to_shared(&mbar[i]);

    if (e == 0) {
#pragma unroll
        for (int i = 0; i < STAGES; i++) mbar_init_(mb[i], 1);
    }

    float v = e0[e];
    et_s[e] = v;
    out[((size_t)b * S_ + 0) * E_ + e] = v;
    __syncthreads();   // mbar init + et_s visible

    const float* wa_base = g_Wa + (size_t)b * S_ * O_;

    if (e == 0) {
#pragma unroll
        for (int i = 0; i < STAGES; i++) {
            mbar_expect_tx_(mb[i], TILE_BYTES_R);
            bulk_g2s_((uint32_t)__cvta_generic_to_shared(&wa_buf[i * O_]),
                      wa_base + (size_t)(1 + i) * O_, TILE_BYTES_R, mb[i]);
        }
    }

    for (int s = 1; s < S_; s++) {
        const int      slot   = (s - 1) % STAGES;
        const uint32_t parity = (uint32_t)(((s - 1) / STAGES) & 1);
        mbar_wait_(mb[slot], parity);

        const float* buf = wa_buf + slot * O_;
        float acc = 0.f;
#pragma unroll 16
        for (int d = 0; d < E_; d++)           // d ascending — order-critical
            acc = fmaf(et_s[d], buf[d * E_ + e], acc);
        float nv = fminf(5.0f, fmaxf(-5.0f, acc));
        out[((size_t)b * S_ + s) * E_ + e] = nv;

        __syncthreads();                       // all done reading buf & et_s
        et_s[e] = nv;
        if (e == 0 && s + STAGES < S_) {
            mbar_expect_tx_(mb[slot], TILE_BYTES_R);
            bulk_g2s_((uint32_t)__cvta_generic_to_shared(&wa_buf[slot * O_]),
                      wa_base + (size_t)(s + STAGES) * O_, TILE_BYTES_R, mb[slot]);
        }
        __syncthreads();                       // et_s published
    }
}

extern "C" void kernel_launch(void* const* d_in, const int* in_sizes, int n_in,
                              void* d_out, int out_size) {
    const float* X  = (const float*)d_in[0];   // [8,512,128]
    const float* W1 = (const float*)d_in[1];   // [512,128]
    const float* b1 = (const float*)d_in[2];   // [512]
    const float* W2 = (const float*)d_in[3];   // [16384,512]
    const float* b2 = (const float*)d_in[4];   // [16384]
    const float* e0 = (const float*)d_in[5];   // [1,128]
    float* out = (float*)d_out;                // [8,512,128] float32

    cudaFuncSetAttribute(recur_kernel,
                         cudaFuncAttributeMaxDynamicSharedMemorySize,
                         STAGES * TILE_BYTES_R);

    hidden_kernel<<<BS_ / 8, 256>>>(X, W1, b1);
    dim3 gridB(O_ / BO, BS_ / BBS);
    wa_kernel<<<gridB, 256>>>(W2, b2);
    recur_kernel<<<B_, E_, STAGES * TILE_BYTES_R>>>(e0, out);
}

// round 6
// speedup vs baseline: 2.3871x; 1.0637x over previous
#include <cuda_runtime.h>
#include <cstdint>

#define B_  8
#define S_  512
#define E_  128
#define H_  512
#define BS_ (B_ * S_)      // 4096
#define O_  (E_ * E_)      // 16384

// Persistent scratch (static __device__ — no runtime allocation)
__device__ float g_hidden[BS_ * H_];                 // 8 MB   [bs][h]
__device__ float g_Wa[(size_t)BS_ * O_];             // 268 MB [bs][o], o = d*128+e

// ---------------------------------------------------------------------------
// XLA/Eigen fast tanh for f32 — exact coefficients and op order (bit-critical)
// ---------------------------------------------------------------------------
__device__ __forceinline__ float tanh_xla(float x) {
    const float kClamp = 7.90531110763549805f;
    float ax = fabsf(x);
    float xc = fmaxf(-kClamp, fminf(kClamp, x));
    float x2 = xc * xc;
    float p = fmaf(x2, -2.76076847742355e-16f, 2.00018790482477e-13f);
    p = fmaf(x2, p, -8.60467152213735e-11f);
    p = fmaf(x2, p,  5.12229709037114e-08f);
    p = fmaf(x2, p,  1.48572235717979e-05f);
    p = fmaf(x2, p,  6.37261928875436e-04f);
    p = fmaf(x2, p,  4.89352455891786e-03f);
    p = xc * p;
    float q = fmaf(x2, 1.19825839466702e-06f, 1.18534705686654e-04f);
    q = fmaf(x2, q, 2.26843463243900e-03f);
    q = fmaf(x2, q, 4.89352518554385e-03f);
    float r = p / q;
    return (ax < 0.0004f) ? x : r;
}

// ---------------------------------------------------------------------------
// packed f32x2 helpers (bitwise: IEEE fma per 32-bit half; pairing is across
// two DIFFERENT outputs — each output's chain stays one sequential chain)
// ---------------------------------------------------------------------------
__device__ __forceinline__ void ffma2_(unsigned long long& d,
                                       unsigned long long a,
                                       unsigned long long b) {
    asm("fma.rn.f32x2 %0, %1, %2, %0;" : "+l"(d) : "l"(a), "l"(b));
}
__device__ __forceinline__ unsigned long long dupf_(float x) {
    unsigned long long r;
    unsigned u = __float_as_uint(x);
    asm("mov.b64 %0, {%1, %1};" : "=l"(r) : "r"(u));
    return r;
}
__device__ __forceinline__ float lo_(unsigned long long a) {
    return __uint_as_float((unsigned)(a & 0xffffffffull));
}
__device__ __forceinline__ float hi_(unsigned long long a) {
    return __uint_as_float((unsigned)(a >> 32));
}

// ---------------------------------------------------------------------------
// mbarrier / cp.async.bulk helpers (recurrence pipeline)
// ---------------------------------------------------------------------------
__device__ __forceinline__ void mbar_init_(uint32_t a, uint32_t cnt) {
    asm volatile("mbarrier.init.shared.b64 [%0], %1;" :: "r"(a), "r"(cnt) : "memory");
}
__device__ __forceinline__ void mbar_expect_tx_(uint32_t a, uint32_t bytes) {
    asm volatile("mbarrier.arrive.expect_tx.shared.b64 _, [%0], %1;"
                 :: "r"(a), "r"(bytes) : "memory");
}
__device__ __forceinline__ void bulk_g2s_(uint32_t dst, const void* src,
                                          uint32_t bytes, uint32_t mbar) {
    asm volatile("cp.async.bulk.shared::cluster.global.mbarrier::complete_tx::bytes "
                 "[%0], [%1], %2, [%3];"
                 :: "r"(dst), "l"(src), "r"(bytes), "r"(mbar) : "memory");
}
__device__ __forceinline__ void mbar_wait_(uint32_t a, uint32_t parity) {
    asm volatile(
        "{\n\t.reg .pred P;\n\t"
        "WL%=:\n\t"
        "mbarrier.try_wait.parity.acquire.cta.shared::cta.b64 P, [%0], %1, 0x989680;\n\t"
        "@P bra WD%=;\n\t"
        "bra WL%=;\n\t"
        "WD%=:\n\t}"
        :: "r"(a), "r"(parity) : "memory");
}

// ---------------------------------------------------------------------------
// Kernel 1 (rewritten): hidden[bs][h] = tanh_xla( seq-e chain + b1[h] )
// 128 blocks x 512 threads (thread = h). 32 bs-rows per block.
// W1 staged transposed to smem in 32-e chunks (register double-buffered);
// X staged transposed+padded so compute-side LDS are broadcast/conflict-free.
// Chain per output: e strictly ascending 0..127, one fmaf chain — unchanged.
// ---------------------------------------------------------------------------
#define HROWS 32
#define XPAD  36

__global__ void __launch_bounds__(512, 1)
hidden_kernel(const float* __restrict__ X,
              const float* __restrict__ W1,
              const float* __restrict__ b1) {
    extern __shared__ float sh[];
    float* x_s = sh;                    // [E_][XPAD]
    float* w1t = sh + E_ * XPAD;        // [32][512]

    const int row0 = blockIdx.x * HROWS;
    const int t    = threadIdx.x;       // h = t

    // stage X transposed: thread (r = t&31, e0 = (t>>5)*8) loads 8 floats
    {
        const int r  = t & 31;
        const int e0 = (t >> 5) * 8;
        const float* src = X + (size_t)(row0 + r) * E_ + e0;
        float4 a = *(const float4*)src;
        float4 c = *(const float4*)(src + 4);
        x_s[(e0 + 0) * XPAD + r] = a.x; x_s[(e0 + 1) * XPAD + r] = a.y;
        x_s[(e0 + 2) * XPAD + r] = a.z; x_s[(e0 + 3) * XPAD + r] = a.w;
        x_s[(e0 + 4) * XPAD + r] = c.x; x_s[(e0 + 5) * XPAD + r] = c.y;
        x_s[(e0 + 6) * XPAD + r] = c.z; x_s[(e0 + 7) * XPAD + r] = c.w;
    }

    float acc[HROWS];
#pragma unroll
    for (int r = 0; r < HROWS; r++) acc[r] = 0.f;

    // prologue: load W1 chunk 0 (row t, e 0..31)
    float4 w4[8];
    {
        const float* wsrc = W1 + (size_t)t * E_;
#pragma unroll
        for (int v = 0; v < 8; v++) w4[v] = ((const float4*)wsrc)[v];
    }

    for (int ec = 0; ec < E_; ec += 32) {
        __syncthreads();            // prev chunk compute done; x_s staged (1st)
#pragma unroll
        for (int v = 0; v < 8; v++) {
            w1t[(v * 4 + 0) * 512 + t] = w4[v].x;
            w1t[(v * 4 + 1) * 512 + t] = w4[v].y;
            w1t[(v * 4 + 2) * 512 + t] = w4[v].z;
            w1t[(v * 4 + 3) * 512 + t] = w4[v].w;
        }
        __syncthreads();
        if (ec + 32 < E_) {         // prefetch next chunk (latency under compute)
            const float* wsrc = W1 + (size_t)t * E_ + ec + 32;
#pragma unroll
            for (int v = 0; v < 8; v++) w4[v] = ((const float4*)wsrc)[v];
        }
#pragma unroll 4
        for (int de = 0; de < 32; de++) {      // e ascending — order-critical
            float wv = w1t[de * 512 + t];
            const float* xrow = x_s + (ec + de) * XPAD;
#pragma unroll
            for (int j = 0; j < 8; j++) {
                float4 xv = *(const float4*)(xrow + 4 * j);
                acc[4 * j + 0] = fmaf(xv.x, wv, acc[4 * j + 0]);
                acc[4 * j + 1] = fmaf(xv.y, wv, acc[4 * j + 1]);
                acc[4 * j + 2] = fmaf(xv.z, wv, acc[4 * j + 2]);
                acc[4 * j + 3] = fmaf(xv.w, wv, acc[4 * j + 3]);
            }
        }
    }

    const float bias = b1[t];
#pragma unroll 4
    for (int r = 0; r < HROWS; r++)
        g_hidden[(size_t)(row0 + r) * H_ + t] = tanh_xla(acc[r] + bias);
}

#define HID_SMEM ((E_ * XPAD + 32 * 512) * 4)   // 83968 bytes

// ---------------------------------------------------------------------------
// Kernel 2: Wa[bs][o] = (seq-h FFMA2 chain of hidden[bs,h]*W2[o,h]) + b2[o]
// Same tiling as round 3 (128o x 128bs, 4x8 o-pair register tile), now with a
// register-staged software pipeline: next tile's LDGs issue before the k-loop
// so L2 latency hides under ~4096 cyc of FFMA2 per SMSP per kc.
// Accumulation: k strictly ascending, one chain per output — unchanged.
// ---------------------------------------------------------------------------
#define BO  128
#define BBS 128
#define KC  32

__global__ void __launch_bounds__(256, 2)
wa_kernel(const float* __restrict__ W2, const float* __restrict__ b2) {
    __shared__ __align__(16) float w_s[KC * BO];    // [k][o]  16 KB
    __shared__ __align__(16) float h_s[KC * BBS];   // [k][bs] 16 KB

    const int obase  = blockIdx.x * BO;
    const int bsbase = blockIdx.y * BBS;
    const int tid    = threadIdx.x;
    const int to = tid & 15;     // o  pairs: 2*to + 32*i, i=0..3
    const int tb = tid >> 4;     // bs pairs: 2*tb + 32*j, j=0..3

    unsigned long long accp[4][8];
#pragma unroll
    for (int i = 0; i < 4; i++)
#pragma unroll
        for (int j = 0; j < 8; j++) accp[i][j] = 0ull;

    const int r   = tid >> 1;          // tile row 0..127
    const int seg = (tid & 1) * 16;    // 16 k-values per thread

    const float* wsrc0 = W2 + (size_t)(obase + r) * H_ + seg;
    const float* hsrc0 = g_hidden + (size_t)(bsbase + r) * H_ + seg;

    // prologue: load tile kc=0 into registers
    float4 wreg[4], hreg[4];
#pragma unroll
    for (int v = 0; v < 4; v++) {
        wreg[v] = *(const float4*)(wsrc0 + v * 4);
        hreg[v] = *(const float4*)(hsrc0 + v * 4);
    }

    for (int kc = 0; kc < H_; kc += KC) {
        __syncthreads();               // previous compute done (smem free)
#pragma unroll
        for (int v = 0; v < 4; v++) {
            w_s[(seg + v * 4 + 0) * BO + r] = wreg[v].x;
            w_s[(seg + v * 4 + 1) * BO + r] = wreg[v].y;
            w_s[(seg + v * 4 + 2) * BO + r] = wreg[v].z;
            w_s[(seg + v * 4 + 3) * BO + r] = wreg[v].w;
            h_s[(seg + v * 4 + 0) * BBS + r] = hreg[v].x;
            h_s[(seg + v * 4 + 1) * BBS + r] = hreg[v].y;
            h_s[(seg + v * 4 + 2) * BBS + r] = hreg[v].z;
            h_s[(seg + v * 4 + 3) * BBS + r] = hreg[v].w;
        }
        __syncthreads();
        if (kc + KC < H_) {            // prefetch next tile — hidden by k-loop
#pragma unroll
            for (int v = 0; v < 4; v++) {
                wreg[v] = *(const float4*)(wsrc0 + kc + KC + v * 4);
                hreg[v] = *(const float4*)(hsrc0 + kc + KC + v * 4);
            }
        }

#pragma unroll 4
        for (int k = 0; k < KC; k++) {   // k strictly ascending — order-critical
            unsigned long long wv2[4];
#pragma unroll
            for (int i = 0; i < 4; i++)
                wv2[i] = *(const unsigned long long*)&w_s[k * BO + 2 * to + 32 * i];
#pragma unroll
            for (int j = 0; j < 4; j++) {
                float2 hv = *(const float2*)&h_s[k * BBS + 2 * tb + 32 * j];
                unsigned long long dl = dupf_(hv.x);
                unsigned long long dh = dupf_(hv.y);
#pragma unroll
                for (int i = 0; i < 4; i++) {
                    ffma2_(accp[i][2 * j + 0], wv2[i], dl);
                    ffma2_(accp[i][2 * j + 1], wv2[i], dh);
                }
            }
        }
    }

    // epilogue: + b2, float2 stores
#pragma unroll
    for (int i = 0; i < 4; i++) {
        int o0 = obase + 2 * to + 32 * i;
        float blo = b2[o0];
        float bhi = b2[o0 + 1];
#pragma unroll
        for (int j = 0; j < 4; j++) {
#pragma unroll
            for (int half = 0; half < 2; half++) {
                int bs = bsbase + 2 * tb + 32 * j + half;
                unsigned long long a = accp[i][2 * j + half];
                float2 res = make_float2(lo_(a) + blo, hi_(a) + bhi);
                *(float2*)&g_Wa[(size_t)bs * O_ + o0] = res;
            }
        }
    }
}

// ---------------------------------------------------------------------------
// Kernel 3: recurrence with triple-buffered TMA bulk prefetch (unchanged).
// ---------------------------------------------------------------------------
#define STAGES 3
#define TILE_BYTES_R (O_ * 4)   // 65536

__global__ void __launch_bounds__(E_, 1)
recur_kernel(const float* __restrict__ e0, float* __restrict__ out) {
    extern __shared__ float wa_buf[];            // STAGES * O_ floats (192 KB)
    __shared__ float et_s[E_];
    __shared__ __align__(8) unsigned long long mbar[STAGES];

    const int b = blockIdx.x;      // 0..7
    const int e = threadIdx.x;     // 0..127

    uint32_t mb[STAGES];
#pragma unroll
    for (int i = 0; i < STAGES; i++)
        mb[i] = (uint32_t)__cvta_generic_to_shared(&mbar[i]);

    if (e == 0) {
#pragma unroll
        for (int i = 0; i < STAGES; i++) mbar_init_(mb[i], 1);
    }

    float v = e0[e];
    et_s[e] = v;
    out[((size_t)b * S_ + 0) * E_ + e] = v;
    __syncthreads();   // mbar init + et_s visible

    const float* wa_base = g_Wa + (size_t)b * S_ * O_;

    if (e == 0) {
#pragma unroll
        for (int i = 0; i < STAGES; i++) {
            mbar_expect_tx_(mb[i], TILE_BYTES_R);
            bulk_g2s_((uint32_t)__cvta_generic_to_shared(&wa_buf[i * O_]),
                      wa_base + (size_t)(1 + i) * O_, TILE_BYTES_R, mb[i]);
        }
    }

    for (int s = 1; s < S_; s++) {
        const int      slot   = (s - 1) % STAGES;
        const uint32_t parity = (uint32_t)(((s - 1) / STAGES) & 1);
        mbar_wait_(mb[slot], parity);

        const float* buf = wa_buf + slot * O_;
        float acc = 0.f;
#pragma unroll 16
        for (int d = 0; d < E_; d++)           // d ascending — order-critical
            acc = fmaf(et_s[d], buf[d * E_ + e], acc);
        float nv = fminf(5.0f, fmaxf(-5.0f, acc));
        out[((size_t)b * S_ + s) * E_ + e] = nv;

        __syncthreads();                       // all done reading buf & et_s
        et_s[e] = nv;
        if (e == 0 && s + STAGES < S_) {
            mbar_expect_tx_(mb[slot], TILE_BYTES_R);
            bulk_g2s_((uint32_t)__cvta_generic_to_shared(&wa_buf[slot * O_]),
                      wa_base + (size_t)(s + STAGES) * O_, TILE_BYTES_R, mb[slot]);
        }
        __syncthreads();                       // et_s published
    }
}

extern "C" void kernel_launch(void* const* d_in, const int* in_sizes, int n_in,
                              void* d_out, int out_size) {
    const float* X  = (const float*)d_in[0];   // [8,512,128]
    const float* W1 = (const float*)d_in[1];   // [512,128]
    const float* b1 = (const float*)d_in[2];   // [512]
    const float* W2 = (const float*)d_in[3];   // [16384,512]
    const float* b2 = (const float*)d_in[4];   // [16384]
    const float* e0 = (const float*)d_in[5];   // [1,128]
    float* out = (float*)d_out;                // [8,512,128] float32

    cudaFuncSetAttribute(hidden_kernel,
                         cudaFuncAttributeMaxDynamicSharedMemorySize, HID_SMEM);
    cudaFuncSetAttribute(recur_kernel,
                         cudaFuncAttributeMaxDynamicSharedMemorySize,
                         STAGES * TILE_BYTES_R);

    hidden_kernel<<<BS_ / HROWS, 512, HID_SMEM>>>(X, W1, b1);
    dim3 gridB(O_ / BO, BS_ / BBS);
    wa_kernel<<<gridB, 256>>>(W2, b2);
    recur_kernel<<<B_, E_, STAGES * TILE_BYTES_R>>>(e0, out);
}

// round 7
// speedup vs baseline: 2.7207x; 1.1398x over previous
#include <cuda_runtime.h>
#include <cstdint>

#define B_  8
#define S_  512
#define E_  128
#define H_  512
#define BS_ (B_ * S_)      // 4096
#define O_  (E_ * E_)      // 16384
#define NCHUNK 4
#define SCH   (S_ / NCHUNK)   // 128 steps per chunk

// Persistent scratch (static __device__ — no runtime allocation)
__device__ float g_hidden[BS_ * H_];                 // 8 MB   [bs][h]
__device__ float g_Wa[(size_t)BS_ * O_];             // 268 MB [bs][o], o = d*128+e
__device__ float g_et[B_ * E_];                      // et carried across chunks

// ---------------------------------------------------------------------------
// XLA/Eigen fast tanh for f32 — exact coefficients and op order (bit-critical)
// ---------------------------------------------------------------------------
__device__ __forceinline__ float tanh_xla(float x) {
    const float kClamp = 7.90531110763549805f;
    float ax = fabsf(x);
    float xc = fmaxf(-kClamp, fminf(kClamp, x));
    float x2 = xc * xc;
    float p = fmaf(x2, -2.76076847742355e-16f, 2.00018790482477e-13f);
    p = fmaf(x2, p, -8.60467152213735e-11f);
    p = fmaf(x2, p,  5.12229709037114e-08f);
    p = fmaf(x2, p,  1.48572235717979e-05f);
    p = fmaf(x2, p,  6.37261928875436e-04f);
    p = fmaf(x2, p,  4.89352455891786e-03f);
    p = xc * p;
    float q = fmaf(x2, 1.19825839466702e-06f, 1.18534705686654e-04f);
    q = fmaf(x2, q, 2.26843463243900e-03f);
    q = fmaf(x2, q, 4.89352518554385e-03f);
    float r = p / q;
    return (ax < 0.0004f) ? x : r;
}

// ---------------------------------------------------------------------------
// packed f32x2 helpers (bitwise: IEEE fma per 32-bit half; pairing is across
// two DIFFERENT outputs — each output's chain stays one sequential chain)
// ---------------------------------------------------------------------------
__device__ __forceinline__ void ffma2_(unsigned long long& d,
                                       unsigned long long a,
                                       unsigned long long b) {
    asm("fma.rn.f32x2 %0, %1, %2, %0;" : "+l"(d) : "l"(a), "l"(b));
}
__device__ __forceinline__ unsigned long long dupf_(float x) {
    unsigned long long r;
    unsigned u = __float_as_uint(x);
    asm("mov.b64 %0, {%1, %1};" : "=l"(r) : "r"(u));
    return r;
}
__device__ __forceinline__ float lo_(unsigned long long a) {
    return __uint_as_float((unsigned)(a & 0xffffffffull));
}
__device__ __forceinline__ float hi_(unsigned long long a) {
    return __uint_as_float((unsigned)(a >> 32));
}

// ---------------------------------------------------------------------------
// async-copy / mbarrier helpers
// ---------------------------------------------------------------------------
__device__ __forceinline__ void cp_async16_(uint32_t dst, const void* src) {
    asm volatile("cp.async.cg.shared.global [%0], [%1], 16;"
                 :: "r"(dst), "l"(src) : "memory");
}
__device__ __forceinline__ void cp_commit_() {
    asm volatile("cp.async.commit_group;" ::: "memory");
}
__device__ __forceinline__ void cp_wait0_() {
    asm volatile("cp.async.wait_group 0;" ::: "memory");
}
__device__ __forceinline__ void mbar_init_(uint32_t a, uint32_t cnt) {
    asm volatile("mbarrier.init.shared.b64 [%0], %1;" :: "r"(a), "r"(cnt) : "memory");
}
__device__ __forceinline__ void mbar_expect_tx_(uint32_t a, uint32_t bytes) {
    asm volatile("mbarrier.arrive.expect_tx.shared.b64 _, [%0], %1;"
                 :: "r"(a), "r"(bytes) : "memory");
}
__device__ __forceinline__ void bulk_g2s_(uint32_t dst, const void* src,
                                          uint32_t bytes, uint32_t mbar) {
    asm volatile("cp.async.bulk.shared::cluster.global.mbarrier::complete_tx::bytes "
                 "[%0], [%1], %2, [%3];"
                 :: "r"(dst), "l"(src), "r"(bytes), "r"(mbar) : "memory");
}
__device__ __forceinline__ void mbar_wait_(uint32_t a, uint32_t parity) {
    asm volatile(
        "{\n\t.reg .pred P;\n\t"
        "WL%=:\n\t"
        "mbarrier.try_wait.parity.acquire.cta.shared::cta.b64 P, [%0], %1, 0x989680;\n\t"
        "@P bra WD%=;\n\t"
        "bra WL%=;\n\t"
        "WD%=:\n\t}"
        :: "r"(a), "r"(parity) : "memory");
}

// ---------------------------------------------------------------------------
// Kernel 1: hidden (unchanged from round 5 — 55us, 3% of total)
// ---------------------------------------------------------------------------
#define HROWS 32
#define XPAD  36

__global__ void __launch_bounds__(512, 1)
hidden_kernel(const float* __restrict__ X,
              const float* __restrict__ W1,
              const float* __restrict__ b1) {
    extern __shared__ float sh[];
    float* x_s = sh;                    // [E_][XPAD]
    float* w1t = sh + E_ * XPAD;        // [32][512]

    const int row0 = blockIdx.x * HROWS;
    const int t    = threadIdx.x;       // h = t

    {
        const int r  = t & 31;
        const int e0 = (t >> 5) * 8;
        const float* src = X + (size_t)(row0 + r) * E_ + e0;
        float4 a = *(const float4*)src;
        float4 c = *(const float4*)(src + 4);
        x_s[(e0 + 0) * XPAD + r] = a.x; x_s[(e0 + 1) * XPAD + r] = a.y;
        x_s[(e0 + 2) * XPAD + r] = a.z; x_s[(e0 + 3) * XPAD + r] = a.w;
        x_s[(e0 + 4) * XPAD + r] = c.x; x_s[(e0 + 5) * XPAD + r] = c.y;
        x_s[(e0 + 6) * XPAD + r] = c.z; x_s[(e0 + 7) * XPAD + r] = c.w;
    }

    float acc[HROWS];
#pragma unroll
    for (int r = 0; r < HROWS; r++) acc[r] = 0.f;

    float4 w4[8];
    {
        const float* wsrc = W1 + (size_t)t * E_;
#pragma unroll
        for (int v = 0; v < 8; v++) w4[v] = ((const float4*)wsrc)[v];
    }

    for (int ec = 0; ec < E_; ec += 32) {
        __syncthreads();
#pragma unroll
        for (int v = 0; v < 8; v++) {
            w1t[(v * 4 + 0) * 512 + t] = w4[v].x;
            w1t[(v * 4 + 1) * 512 + t] = w4[v].y;
            w1t[(v * 4 + 2) * 512 + t] = w4[v].z;
            w1t[(v * 4 + 3) * 512 + t] = w4[v].w;
        }
        __syncthreads();
        if (ec + 32 < E_) {
            const float* wsrc = W1 + (size_t)t * E_ + ec + 32;
#pragma unroll
            for (int v = 0; v < 8; v++) w4[v] = ((const float4*)wsrc)[v];
        }
#pragma unroll 4
        for (int de = 0; de < 32; de++) {      // e ascending — order-critical
            float wv = w1t[de * 512 + t];
            const float* xrow = x_s + (ec + de) * XPAD;
#pragma unroll
            for (int j = 0; j < 8; j++) {
                float4 xv = *(const float4*)(xrow + 4 * j);
                acc[4 * j + 0] = fmaf(xv.x, wv, acc[4 * j + 0]);
                acc[4 * j + 1] = fmaf(xv.y, wv, acc[4 * j + 1]);
                acc[4 * j + 2] = fmaf(xv.z, wv, acc[4 * j + 2]);
                acc[4 * j + 3] = fmaf(xv.w, wv, acc[4 * j + 3]);
            }
        }
    }

    const float bias = b1[t];
#pragma unroll 4
    for (int r = 0; r < HROWS; r++)
        g_hidden[(size_t)(row0 + r) * H_ + t] = tanh_xla(acc[r] + bias);
}

#define HID_SMEM ((E_ * XPAD + 32 * 512) * 4)   // 83968 bytes

// ---------------------------------------------------------------------------
// Kernel 2 (chunked): Wa for s in [chunk*128, chunk*128+128), all b, all o.
//   Wa[bs][o] = (seq-h FFMA2 chain of hidden[bs,h]*W2[o,h]) + b2[o]
// Double-buffered: h tile via cp.async (g->smem, [row][k] layout, no regs);
// w tile via register staging into ping-pong transposed smem. One sync/tile.
// Accumulation: k strictly ascending, one chain per output — order-critical.
// ---------------------------------------------------------------------------
#define BO  128
#define KC  32
#define NT  (H_ / KC)   // 16 tiles

__global__ void __launch_bounds__(256, 2)
wa_kernel(const float* __restrict__ W2, const float* __restrict__ b2, int chunk) {
    __shared__ __align__(16) float w_s[2][KC][BO];    // 2 x 16 KB, [k][o]
    __shared__ __align__(16) float h_s[2][BO][KC];    // 2 x 16 KB, [bs][k]

    const int obase  = blockIdx.x * BO;
    const int bsbase = blockIdx.y * S_ + chunk * SCH;   // b = blockIdx.y
    const int tid    = threadIdx.x;
    const int to = tid & 15;     // o  pairs: 2*to + 32*i
    const int tb = tid >> 4;     // bs pairs: 2*tb + 32*j

    unsigned long long accp[4][8];
#pragma unroll
    for (int i = 0; i < 4; i++)
#pragma unroll
        for (int j = 0; j < 8; j++) accp[i][j] = 0ull;

    const int r   = tid >> 1;          // tile row 0..127
    const int seg = (tid & 1) * 16;    // 16 k-values per thread (w staging)

    const float*    wsrc0 = W2 + (size_t)(obase + r) * H_ + seg;
    const uint32_t  h_smem0 = (uint32_t)__cvta_generic_to_shared(&h_s[0][0][0]);

    // h cp.async: 1024 16B chunks per tile, 4 per thread
    auto stage_h = [&](int buf, int kc) {
#pragma unroll
        for (int q = 0; q < 4; q++) {
            int id   = q * 256 + tid;
            int row  = id >> 3;            // 0..127
            int c16  = (id & 7) * 4;       // float offset within row
            const float* src = g_hidden + (size_t)(bsbase + row) * H_ + kc + c16;
            uint32_t dst = h_smem0 + ((buf * BO + row) * KC + c16) * 4;
            cp_async16_(dst, src);
        }
        cp_commit_();
    };

    // prologue: tile 0
    stage_h(0, 0);
    float4 wreg[4];
#pragma unroll
    for (int v = 0; v < 4; v++) wreg[v] = *(const float4*)(wsrc0 + v * 4);

    for (int it = 0; it < NT; it++) {
        const int cur = it & 1;
        // store w tile it (transposed) — w_s[cur] free: last read at it-2
#pragma unroll
        for (int v = 0; v < 4; v++) {
            w_s[cur][seg + v * 4 + 0][r] = wreg[v].x;
            w_s[cur][seg + v * 4 + 1][r] = wreg[v].y;
            w_s[cur][seg + v * 4 + 2][r] = wreg[v].z;
            w_s[cur][seg + v * 4 + 3][r] = wreg[v].w;
        }
        cp_wait0_();              // this thread's h tile 'it' copies done
        __syncthreads();          // everyone's h + w visible; prev bufs free

        if (it + 1 < NT) {        // start next tile: latency hides under k-loop
            stage_h(cur ^ 1, (it + 1) * KC);
#pragma unroll
            for (int v = 0; v < 4; v++)
                wreg[v] = *(const float4*)(wsrc0 + (it + 1) * KC + v * 4);
        }

#pragma unroll 4
        for (int k = 0; k < KC; k++) {   // k strictly ascending — order-critical
            unsigned long long wv2[4];
#pragma unroll
            for (int i = 0; i < 4; i++)
                wv2[i] = *(const unsigned long long*)&w_s[cur][k][2 * to + 32 * i];
#pragma unroll
            for (int j = 0; j < 4; j++) {
                unsigned long long dl = dupf_(h_s[cur][2 * tb + 32 * j + 0][k]);
                unsigned long long dh = dupf_(h_s[cur][2 * tb + 32 * j + 1][k]);
#pragma unroll
                for (int i = 0; i < 4; i++) {
                    ffma2_(accp[i][2 * j + 0], wv2[i], dl);
                    ffma2_(accp[i][2 * j + 1], wv2[i], dh);
                }
            }
        }
    }

    // epilogue: + b2, float2 stores
#pragma unroll
    for (int i = 0; i < 4; i++) {
        int o0 = obase + 2 * to + 32 * i;
        float blo = b2[o0];
        float bhi = b2[o0 + 1];
#pragma unroll
        for (int j = 0; j < 4; j++) {
#pragma unroll
            for (int half = 0; half < 2; half++) {
                int bs = bsbase + 2 * tb + 32 * j + half;
                unsigned long long a = accp[i][2 * j + half];
                float2 res = make_float2(lo_(a) + blo, hi_(a) + bhi);
                *(float2*)&g_Wa[(size_t)bs * O_ + o0] = res;
            }
        }
    }
}

// ---------------------------------------------------------------------------
// Kernel 3 (chunked): recurrence steps s in [max(1,chunk*128), chunk*128+128).
// Triple-buffered TMA prefetch; et carried via g_et across chunks (exact copy).
// Arithmetic identical: seq-d FMA chain from smem, clip.
// ---------------------------------------------------------------------------
#define STAGES 3
#define TILE_BYTES_R (O_ * 4)   // 65536

__global__ void __launch_bounds__(E_, 1)
recur_kernel(const float* __restrict__ e0, float* __restrict__ out, int chunk) {
    extern __shared__ float wa_buf[];            // STAGES * O_ floats (192 KB)
    __shared__ float et_s[E_];
    __shared__ __align__(8) unsigned long long mbar[STAGES];

    const int b = blockIdx.x;      // 0..7
    const int e = threadIdx.x;     // 0..127

    uint32_t mb[STAGES];
#pragma unroll
    for (int i = 0; i < STAGES; i++)
        mb[i] = (uint32_t)__cvta_generic_to_shared(&mbar[i]);

    if (e == 0) {
#pragma unroll
        for (int i = 0; i < STAGES; i++) mbar_init_(mb[i], 1);
    }

    const int s_begin = (chunk == 0) ? 1 : chunk * SCH;
    const int s_end   = chunk * SCH + SCH;

    float v;
    if (chunk == 0) {
        v = e0[e];
        out[((size_t)b * S_ + 0) * E_ + e] = v;
    } else {
        v = g_et[b * E_ + e];
    }
    et_s[e] = v;
    __syncthreads();   // mbar init + et_s visible

    const float* wa_base = g_Wa + (size_t)b * S_ * O_;

    if (e == 0) {
#pragma unroll
        for (int i = 0; i < STAGES; i++) {
            if (s_begin + i < s_end) {
                mbar_expect_tx_(mb[i], TILE_BYTES_R);
                bulk_g2s_((uint32_t)__cvta_generic_to_shared(&wa_buf[i * O_]),
                          wa_base + (size_t)(s_begin + i) * O_, TILE_BYTES_R, mb[i]);
            }
        }
    }

    for (int s = s_begin; s < s_end; s++) {
        const int      i      = s - s_begin;
        const int      slot   = i % STAGES;
        const uint32_t parity = (uint32_t)((i / STAGES) & 1);
        mbar_wait_(mb[slot], parity);

        const float* buf = wa_buf + slot * O_;
        float acc = 0.f;
#pragma unroll 16
        for (int d = 0; d < E_; d++)           // d ascending — order-critical
            acc = fmaf(et_s[d], buf[d * E_ + e], acc);
        float nv = fminf(5.0f, fmaxf(-5.0f, acc));
        out[((size_t)b * S_ + s) * E_ + e] = nv;

        __syncthreads();                       // all done reading buf & et_s
        et_s[e] = nv;
        if (e == 0 && s + STAGES < s_end) {
            mbar_expect_tx_(mb[slot], TILE_BYTES_R);
            bulk_g2s_((uint32_t)__cvta_generic_to_shared(&wa_buf[slot * O_]),
                      wa_base + (size_t)(s + STAGES) * O_, TILE_BYTES_R, mb[slot]);
        }
        __syncthreads();                       // et_s published
        v = nv;
    }

    g_et[b * E_ + e] = v;                      // exact fp32 pass-through
}

// ---------------------------------------------------------------------------
// Launch: fork recur chunks onto a second stream so recur chunk c overlaps
// wa chunk c+1. Stream/events created once in the first (uncaptured) call.
// ---------------------------------------------------------------------------
extern "C" void kernel_launch(void* const* d_in, const int* in_sizes, int n_in,
                              void* d_out, int out_size) {
    const float* X  = (const float*)d_in[0];   // [8,512,128]
    const float* W1 = (const float*)d_in[1];   // [512,128]
    const float* b1 = (const float*)d_in[2];   // [512]
    const float* W2 = (const float*)d_in[3];   // [16384,512]
    const float* b2 = (const float*)d_in[4];   // [16384]
    const float* e0 = (const float*)d_in[5];   // [1,128]
    float* out = (float*)d_out;                // [8,512,128] float32

    static cudaStream_t s2 = nullptr;
    static cudaEvent_t  ev_wa[NCHUNK];
    static cudaEvent_t  ev_join;
    if (s2 == nullptr) {
        cudaStreamCreateWithFlags(&s2, cudaStreamNonBlocking);
        for (int c = 0; c < NCHUNK; c++)
            cudaEventCreateWithFlags(&ev_wa[c], cudaEventDisableTiming);
        cudaEventCreateWithFlags(&ev_join, cudaEventDisableTiming);
        cudaFuncSetAttribute(hidden_kernel,
                             cudaFuncAttributeMaxDynamicSharedMemorySize, HID_SMEM);
        cudaFuncSetAttribute(recur_kernel,
                             cudaFuncAttributeMaxDynamicSharedMemorySize,
                             STAGES * TILE_BYTES_R);
    }

    hidden_kernel<<<BS_ / HROWS, 512, HID_SMEM>>>(X, W1, b1);

    dim3 gridW(O_ / BO, B_);   // 128 o-tiles x 8 batches per chunk
    for (int c = 0; c < NCHUNK; c++) {
        wa_kernel<<<gridW, 256>>>(W2, b2, c);
        cudaEventRecord(ev_wa[c], 0);
    }
    for (int c = 0; c < NCHUNK; c++) {
        cudaStreamWaitEvent(s2, ev_wa[c], 0);
        recur_kernel<<<B_, E_, STAGES * TILE_BYTES_R, s2>>>(e0, out, c);
    }
    cudaEventRecord(ev_join, s2);
    cudaStreamWaitEvent(0, ev_join, 0);
}